// round 6
// baseline (speedup 1.0000x reference)
#include <cuda_runtime.h>

#define DN 32
#define DE 16
#define DH 64
#define DO 32

// Precomputed per-node x@W1[:32,:] + b1  (100000 x 64 f32 = 25.6 MB, L2-resident)
__device__ __align__(16) float g_pre[100000 * DH];
__device__ int g_which;  // which candidate buffer is edge_index (0 = A, 1 = B)
__device__ int g_is64;   // 1 if edge_index is int64, 0 if int32

__global__ void zero_out(float4* __restrict__ out, int n4) {
  int i = blockIdx.x * blockDim.x + threadIdx.x;
  if (i < n4) out[i] = make_float4(0.f, 0.f, 0.f, 0.f);
}

// Classify the two size-ambiguous buffers: which one holds indices, and width.
__global__ void detect(const unsigned* __restrict__ A,
                       const unsigned* __restrict__ B, unsigned n_nodes) {
  const unsigned* c[2] = {A, B};
  int which = 1, is64 = 1;  // fallback = dict order (A=x, B=edge_index, int64)
  for (int cand = 0; cand < 2; cand++) {
    bool all_small = true;
    for (int i = 0; i < 1024; i++)
      if (c[cand][i] >= n_nodes) { all_small = false; break; }
    if (all_small) {                 // this is the index array
      which = cand;
      bool odd_zero = true;
      for (int i = 1; i < 1024; i += 2)
        if (c[cand][i] != 0u) { odd_zero = false; break; }
      is64 = odd_zero ? 1 : 0;
      break;
    }
  }
  g_which = which;
  g_is64 = is64;
}

// 4 nodes per 256-thread block; thread j of each 64-group computes pre[node][j].
__global__ __launch_bounds__(256) void precompute(
    const float* __restrict__ candA, const float* __restrict__ candB,
    const float* __restrict__ W1, const float* __restrict__ b1, int n_nodes) {
  __shared__ __align__(16) float sW[DN * DH];
  __shared__ float sb[DH];
  int t = threadIdx.x;
  for (int i = t; i < DN * DH; i += 256) sW[i] = W1[i];  // W1 rows 0..31
  if (t < DH) sb[t] = b1[t];
  __syncthreads();
  const float* x = (g_which == 0) ? candB : candA;  // x = the non-index buffer
  int node = blockIdx.x * 4 + (t >> 6);
  if (node >= n_nodes) return;
  int j = t & 63;
  const float* xr = x + node * DN;
  float acc = sb[j];
#pragma unroll
  for (int i = 0; i < DN; i++) acc = fmaf(__ldg(xr + i), sW[i * DH + j], acc);
  g_pre[node * DH + j] = acc;
}

__device__ __forceinline__ void red_add_v4(float* p, float a, float b, float c, float d) {
  asm volatile("red.global.v4.f32.add [%0], {%1,%2,%3,%4};"
               :: "l"(p), "f"(a), "f"(b), "f"(c), "f"(d) : "memory");
}

// One thread per edge: h = pre[col]; h += ea@W1b; o = b2 + relu(h)@W2; scatter.
__global__ __launch_bounds__(128) void edge_mlp(
    const void* __restrict__ candA, const void* __restrict__ candB,
    const float* __restrict__ ea, const float* __restrict__ W1,
    const float* __restrict__ W2, const float* __restrict__ b2,
    float* __restrict__ out, int E, unsigned n_nodes) {
  __shared__ __align__(16) float sW1b[DE * DH];  // W1 rows 32..47
  __shared__ __align__(16) float sW2[DH * DO];
  __shared__ __align__(16) float sb2[DO];
  int t = threadIdx.x;
  for (int i = t; i < DE * DH; i += 128) sW1b[i] = W1[DN * DH + i];
  for (int i = t; i < DH * DO; i += 128) sW2[i] = W2[i];
  if (t < DO) sb2[t] = b2[t];
  __syncthreads();

  int e = blockIdx.x * 128 + t;
  if (e >= E) return;

  const void* eip = (g_which == 0) ? candA : candB;
  unsigned row, col;
  if (g_is64) {
    const long long* p = (const long long*)eip;
    row = (unsigned)p[e];
    col = (unsigned)p[E + e];
  } else {
    const int* p = (const int*)eip;
    row = (unsigned)p[e];
    col = (unsigned)p[E + e];
  }
  if (row >= n_nodes) row = 0;  // safety: never crash, surface as rel_err
  if (col >= n_nodes) col = 0;

  float h[DH];
  const float4* pre4 = reinterpret_cast<const float4*>(g_pre + (size_t)col * DH);
#pragma unroll
  for (int q = 0; q < DH / 4; q++) {
    float4 v = pre4[q];
    h[4*q] = v.x; h[4*q+1] = v.y; h[4*q+2] = v.z; h[4*q+3] = v.w;
  }

  float a[DE];
  const float4* ea4 = reinterpret_cast<const float4*>(ea + (size_t)e * DE);
#pragma unroll
  for (int q = 0; q < DE / 4; q++) {
    float4 v = ea4[q];
    a[4*q] = v.x; a[4*q+1] = v.y; a[4*q+2] = v.z; a[4*q+3] = v.w;
  }

  // h += ea @ W1b  (16x64 = 1024 FMA)
#pragma unroll
  for (int i = 0; i < DE; i++) {
    float ai = a[i];
    const float4* w = reinterpret_cast<const float4*>(sW1b + i * DH);
#pragma unroll
    for (int q = 0; q < DH / 4; q++) {
      float4 wv = w[q];
      h[4*q]   = fmaf(ai, wv.x, h[4*q]);
      h[4*q+1] = fmaf(ai, wv.y, h[4*q+1]);
      h[4*q+2] = fmaf(ai, wv.z, h[4*q+2]);
      h[4*q+3] = fmaf(ai, wv.w, h[4*q+3]);
    }
  }

  // o = b2 + relu(h) @ W2  (64x32 = 2048 FMA)
  float o[DO];
  const float4* b24 = reinterpret_cast<const float4*>(sb2);
#pragma unroll
  for (int q = 0; q < DO / 4; q++) {
    float4 v = b24[q];
    o[4*q] = v.x; o[4*q+1] = v.y; o[4*q+2] = v.z; o[4*q+3] = v.w;
  }
#pragma unroll
  for (int k = 0; k < DH; k++) {
    float hk = fmaxf(h[k], 0.0f);
    const float4* w = reinterpret_cast<const float4*>(sW2 + k * DO);
#pragma unroll
    for (int q = 0; q < DO / 4; q++) {
      float4 wv = w[q];
      o[4*q]   = fmaf(hk, wv.x, o[4*q]);
      o[4*q+1] = fmaf(hk, wv.y, o[4*q+1]);
      o[4*q+2] = fmaf(hk, wv.z, o[4*q+2]);
      o[4*q+3] = fmaf(hk, wv.w, o[4*q+3]);
    }
  }

  float* op = out + (size_t)row * DO;
#pragma unroll
  for (int q = 0; q < DO / 4; q++)
    red_add_v4(op + 4*q, o[4*q], o[4*q+1], o[4*q+2], o[4*q+3]);
}

extern "C" void kernel_launch(void* const* d_in, const int* in_sizes, int n_in,
                              void* d_out, int out_size) {
  // Identify inputs by element count; only x vs edge_index is ambiguous.
  int iW1 = 3, ib1 = 4, iW2 = 5, ib2 = 6;     // dict-order defaults
  int big[3], nbig = 0;
  for (int i = 0; i < n_in; i++) {
    int s = in_sizes[i];
    if      (s == (DN + DE) * DH) iW1 = i;
    else if (s == DH)             ib1 = i;
    else if (s == DH * DO)        iW2 = i;
    else if (s == DO)             ib2 = i;
    else if (nbig < 3)            big[nbig++] = i;
  }
  // Largest remaining buffer = edge_attr; the other two = {x, edge_index}.
  int iea = big[0];
  for (int k = 1; k < nbig; k++)
    if (in_sizes[big[k]] > in_sizes[iea]) iea = big[k];
  int cA = -1, cB = -1;
  for (int k = 0; k < nbig; k++) {
    if (big[k] == iea) continue;
    if (cA < 0) cA = big[k]; else cB = big[k];
  }

  const float* ea = (const float*)d_in[iea];
  const float* W1 = (const float*)d_in[iW1];
  const float* b1 = (const float*)d_in[ib1];
  const float* W2 = (const float*)d_in[iW2];
  const float* b2 = (const float*)d_in[ib2];
  float* out = (float*)d_out;

  int E = in_sizes[iea] / DE;                 // 1,600,000
  int N = in_sizes[cA] / DN;                  // 100,000 (both candidates: 3.2M elems)

  detect<<<1, 1>>>((const unsigned*)d_in[cA], (const unsigned*)d_in[cB], (unsigned)N);
  int n4 = out_size / 4;
  zero_out<<<(n4 + 255) / 256, 256>>>((float4*)out, n4);
  precompute<<<(N + 3) / 4, 256>>>((const float*)d_in[cA], (const float*)d_in[cB],
                                   W1, b1, N);
  edge_mlp<<<(E + 127) / 128, 128>>>(d_in[cA], d_in[cB], ea, W1, W2, b2, out, E,
                                     (unsigned)N);
}